// round 2
// baseline (speedup 1.0000x reference)
#include <cuda_runtime.h>
#include <math.h>

// ---------------- problem constants ----------------
#define BATCH 4
#define SEQ   4096
#define HID_  1024
#define LC    1024          // compressed length (SEQ/RATIO)
#define KSEL  512           // selected tokens
#define WIN   256           // window size
#define NWIN  16            // windows that survive truncation
#define HC    4096          // RATIO*HID

static const long N_TOK   = (long)BATCH * SEQ;          // 16384
static const long SZ_FULL = N_TOK * HID_;               // 16,777,216
static const long SZ_COMP = (long)BATCH * LC * HID_;    // 4,194,304
static const long SZ_SC   = (long)BATCH * LC * LC;      // 4,194,304
static const long SZ_SEL  = (long)BATCH * KSEL * HID_;  // 2,097,152
static const long SZ_SS   = (long)BATCH * KSEL * KSEL;  // 1,048,576
static const long SZ_SW   = (long)BATCH * NWIN * WIN * WIN; // 4,194,304

// scratch layout (floats)
#define OFF_QF     0L
#define OFF_KF     (OFF_QF + SZ_FULL)
#define OFF_VF     (OFF_KF + SZ_FULL)
#define OFF_COMP   (OFF_VF + SZ_FULL)
#define OFF_QC     (OFF_COMP + SZ_COMP)
#define OFF_KC     (OFF_QC + SZ_COMP)
#define OFF_VC     (OFF_KC + SZ_COMP)
#define OFF_SC     (OFF_VC + SZ_COMP)
#define OFF_CPV    (OFF_SC + SZ_SC)
#define OFF_SQ     (OFF_CPV + SZ_COMP)
#define OFF_SK     (OFF_SQ + SZ_SEL)
#define OFF_SV     (OFF_SK + SZ_SEL)
#define OFF_SS     (OFF_SV + SZ_SEL)
#define OFF_SPV    (OFF_SS + SZ_SS)
#define OFF_SW     (OFF_SPV + SZ_SEL)
#define OFF_WPV    (OFF_SW + SZ_SW)
#define OFF_O      (OFF_WPV + SZ_FULL)
#define OFF_GATES  (OFF_O + SZ_FULL)
#define OFF_SCORES (OFF_GATES + N_TOK*3)
#define SCRATCH_TOTAL (OFF_SCORES + N_TOK)

__device__ float g_scratch[SCRATCH_TOTAL];
__device__ int   g_idx[BATCH * KSEL];

// ---------------- generic tiled fp32 GEMM ----------------
// C = alpha * A * op(B) [+ bias] [+ C] [* gate(row)]
// 2-level batch indexing: z -> (zo = z/zdiv, zi = z%zdiv); each operand offset
// = zo*so + zi*si.  gate index = gateBase + row*3 + gcomp.
struct GemmP {
    const float *A, *B, *bias, *gate;
    float *C;
    int M, N, K, lda, ldb, ldc;
    float alpha;
    int transB, accumulate, zdiv, gcomp;
    long aso, asi, bso, bsi, cso, csi, gso, gsi;
};

__global__ void __launch_bounds__(256) gemm_k(GemmP p) {
    const int tid = threadIdx.x;
    const int z = blockIdx.z;
    const long zo = z / p.zdiv, zi = z - zo * (long)p.zdiv;
    const float* A  = p.A + zo * p.aso + zi * p.asi;
    const float* Bm = p.B + zo * p.bso + zi * p.bsi;
    float* C        = p.C + zo * p.cso + zi * p.csi;

    const int rowBase = blockIdx.y * 64;
    const int colBase = blockIdx.x * 64;

    __shared__ float As[16][64];
    __shared__ float Bs[16][64];

    float acc[4][4];
#pragma unroll
    for (int i = 0; i < 4; i++)
#pragma unroll
        for (int j = 0; j < 4; j++) acc[i][j] = 0.f;

    const int tx = tid & 15, ty = tid >> 4;
    const int la_m = tid >> 2, la_k = (tid & 3) * 4;   // A tile load coords
    const int lb_nt_n = tid >> 2, lb_nt_k = (tid & 3) * 4;
    const int lb_nn_k = tid >> 4, lb_nn_n = (tid & 15) * 4;

    for (int kt = 0; kt < p.K; kt += 16) {
        float4 av = *(const float4*)(A + (long)(rowBase + la_m) * p.lda + kt + la_k);
        As[la_k + 0][la_m] = av.x;
        As[la_k + 1][la_m] = av.y;
        As[la_k + 2][la_m] = av.z;
        As[la_k + 3][la_m] = av.w;
        if (p.transB) {   // B is (N,K) row-major, need B^T
            float4 bv = *(const float4*)(Bm + (long)(colBase + lb_nt_n) * p.ldb + kt + lb_nt_k);
            Bs[lb_nt_k + 0][lb_nt_n] = bv.x;
            Bs[lb_nt_k + 1][lb_nt_n] = bv.y;
            Bs[lb_nt_k + 2][lb_nt_n] = bv.z;
            Bs[lb_nt_k + 3][lb_nt_n] = bv.w;
        } else {          // B is (K,N) row-major
            float4 bv = *(const float4*)(Bm + (long)(kt + lb_nn_k) * p.ldb + colBase + lb_nn_n);
            *(float4*)&Bs[lb_nn_k][lb_nn_n] = bv;
        }
        __syncthreads();
#pragma unroll
        for (int kk = 0; kk < 16; kk++) {
            float a[4], b[4];
#pragma unroll
            for (int i = 0; i < 4; i++) a[i] = As[kk][ty * 4 + i];
#pragma unroll
            for (int j = 0; j < 4; j++) b[j] = Bs[kk][tx * 4 + j];
#pragma unroll
            for (int i = 0; i < 4; i++)
#pragma unroll
                for (int j = 0; j < 4; j++) acc[i][j] += a[i] * b[j];
        }
        __syncthreads();
    }

    const float* g = p.gate ? (p.gate + zo * p.gso + zi * p.gsi) : nullptr;
#pragma unroll
    for (int i = 0; i < 4; i++) {
        int row = rowBase + ty * 4 + i;
        float gv = g ? g[(long)row * 3 + p.gcomp] : 1.f;
#pragma unroll
        for (int j = 0; j < 4; j++) {
            int col = colBase + tx * 4 + j;
            float v = p.alpha * acc[i][j];
            if (p.bias) v += p.bias[col];
            if (p.accumulate) v += C[(long)row * p.ldc + col];
            v *= gv;
            C[(long)row * p.ldc + col] = v;
        }
    }
}

static void run_gemm(const float* A, const float* B, const float* bias, const float* gate,
                     float* C, int M, int N, int K, int lda, int ldb, int ldc,
                     float alpha, int transB, int accum,
                     int nz, int zdiv,
                     long aso, long asi, long bso, long bsi, long cso, long csi,
                     long gso, long gsi, int gcomp) {
    GemmP p;
    p.A = A; p.B = B; p.bias = bias; p.gate = gate; p.C = C;
    p.M = M; p.N = N; p.K = K; p.lda = lda; p.ldb = ldb; p.ldc = ldc;
    p.alpha = alpha; p.transB = transB; p.accumulate = accum;
    p.zdiv = zdiv; p.gcomp = gcomp;
    p.aso = aso; p.asi = asi; p.bso = bso; p.bsi = bsi;
    p.cso = cso; p.csi = csi; p.gso = gso; p.gsi = gsi;
    dim3 grid(N / 64, M / 64, nz);
    gemm_k<<<grid, 256>>>(p);
}

// ---------------- gates + scores (fused) ----------------
__global__ void gates_scores_k(const float* __restrict__ x,
                               const float* __restrict__ Wg, const float* __restrict__ bg,
                               const float* __restrict__ Ws, const float* __restrict__ bs,
                               float* __restrict__ gates, float* __restrict__ scores) {
    int warp = threadIdx.x >> 5, lane = threadIdx.x & 31;
    long t = (long)blockIdx.x * 4 + warp;
    if (t >= N_TOK) return;
    const float* xr = x + t * HID_;
    float a0 = 0.f, a1 = 0.f, a2 = 0.f, a3 = 0.f;
    for (int d = lane; d < HID_; d += 32) {
        float xv = xr[d];
        a0 += xv * Wg[d * 3 + 0];
        a1 += xv * Wg[d * 3 + 1];
        a2 += xv * Wg[d * 3 + 2];
        a3 += xv * Ws[d];
    }
#pragma unroll
    for (int o = 16; o > 0; o >>= 1) {
        a0 += __shfl_down_sync(0xffffffffu, a0, o);
        a1 += __shfl_down_sync(0xffffffffu, a1, o);
        a2 += __shfl_down_sync(0xffffffffu, a2, o);
        a3 += __shfl_down_sync(0xffffffffu, a3, o);
    }
    if (lane == 0) {
        float g0 = 1.f / (1.f + expf(-(a0 + bg[0])));
        float g1 = 1.f / (1.f + expf(-(a1 + bg[1])));
        float g2 = 1.f / (1.f + expf(-(a2 + bg[2])));
        float s = g0 + g1 + g2 + 1e-6f;
        gates[t * 3 + 0] = g0 / s;
        gates[t * 3 + 1] = g1 / s;
        gates[t * 3 + 2] = g2 / s;
        scores[t] = a3 + bs[0];
    }
}

// ---------------- exact top-k (per batch, bitonic) ----------------
__device__ __forceinline__ bool before_f(float sa, int ia, float sb, int ib) {
    return (sa > sb) || (sa == sb && ia < ib);   // jax top_k order: value desc, idx asc
}

__global__ void __launch_bounds__(512) topk_k(const float* __restrict__ scores, int* __restrict__ idx_out) {
    __shared__ float s[SEQ];
    __shared__ int   id[SEQ];
    __shared__ int   sel[KSEL];
    int b = blockIdx.x, tid = threadIdx.x;
    for (int i = tid; i < SEQ; i += 512) { s[i] = scores[(long)b * SEQ + i]; id[i] = i; }
    __syncthreads();
    for (int k = 2; k <= SEQ; k <<= 1) {
        for (int j = k >> 1; j > 0; j >>= 1) {
            for (int i = tid; i < SEQ; i += 512) {
                int ixj = i ^ j;
                if (ixj > i) {
                    bool up = ((i & k) == 0);
                    bool ib = before_f(s[i], id[i], s[ixj], id[ixj]);
                    if (up ? !ib : ib) {
                        float ts = s[i]; s[i] = s[ixj]; s[ixj] = ts;
                        int   ti = id[i]; id[i] = id[ixj]; id[ixj] = ti;
                    }
                }
            }
            __syncthreads();
        }
    }
    if (tid < KSEL) sel[tid] = id[tid];
    __syncthreads();
    for (int k = 2; k <= KSEL; k <<= 1) {
        for (int j = k >> 1; j > 0; j >>= 1) {
            int i = tid;
            if (i < KSEL) {
                int ixj = i ^ j;
                if (ixj > i) {
                    bool up = ((i & k) == 0);
                    if (up ? (sel[i] > sel[ixj]) : (sel[i] < sel[ixj])) {
                        int t = sel[i]; sel[i] = sel[ixj]; sel[ixj] = t;
                    }
                }
            }
            __syncthreads();
        }
    }
    if (tid < KSEL) idx_out[b * KSEL + tid] = sel[tid];
}

// ---------------- gather selected Q/K/V ----------------
__global__ void gather_k(const float* __restrict__ Q, const float* __restrict__ K,
                         const float* __restrict__ V, const int* __restrict__ idx,
                         float* __restrict__ sq, float* __restrict__ sk, float* __restrict__ sv) {
    int r = blockIdx.x;                 // 0 .. BATCH*KSEL-1
    int b = r >> 9;
    int src = idx[r];
    long so = ((long)b * SEQ + src) * HID_;
    long dofs = (long)r * HID_;
    for (int d = threadIdx.x; d < HID_; d += blockDim.x) {
        sq[dofs + d] = Q[so + d];
        sk[dofs + d] = K[so + d];
        sv[dofs + d] = V[so + d];
    }
}

// ---------------- row softmax (in place) ----------------
__global__ void softmax_k(float* __restrict__ S, int N) {
    long base = (long)blockIdx.x * N;
    int tid = threadIdx.x;
    __shared__ float red[256];
    float m = -1e30f;
    for (int i = tid; i < N; i += 256) m = fmaxf(m, S[base + i]);
    red[tid] = m; __syncthreads();
    for (int o = 128; o > 0; o >>= 1) { if (tid < o) red[tid] = fmaxf(red[tid], red[tid + o]); __syncthreads(); }
    m = red[0]; __syncthreads();
    float sum = 0.f;
    for (int i = tid; i < N; i += 256) {
        float e = expf(S[base + i] - m);
        S[base + i] = e;
        sum += e;
    }
    red[tid] = sum; __syncthreads();
    for (int o = 128; o > 0; o >>= 1) { if (tid < o) red[tid] += red[tid + o]; __syncthreads(); }
    float inv = 1.f / red[0];
    for (int i = tid; i < N; i += 256) S[base + i] *= inv;
}

// ---------------- residual + layernorm ----------------
__global__ void final_ln_k(const float* __restrict__ O, const float* __restrict__ x,
                           float* __restrict__ out) {
    long base = (long)blockIdx.x * HID_;
    int tid = threadIdx.x;
    float y[4];
    float s = 0.f, ss = 0.f;
#pragma unroll
    for (int i = 0; i < 4; i++) {
        int c = tid + i * 256;
        float v = 0.5f * (O[base + c] + x[base + c]);
        y[i] = v; s += v; ss += v * v;
    }
    __shared__ float rs[32], rss[32];
    int lane = tid & 31, warp = tid >> 5;
#pragma unroll
    for (int o = 16; o > 0; o >>= 1) {
        s  += __shfl_down_sync(0xffffffffu, s, o);
        ss += __shfl_down_sync(0xffffffffu, ss, o);
    }
    if (lane == 0) { rs[warp] = s; rss[warp] = ss; }
    __syncthreads();
    if (warp == 0) {
        s  = (lane < 8) ? rs[lane]  : 0.f;
        ss = (lane < 8) ? rss[lane] : 0.f;
#pragma unroll
        for (int o = 4; o > 0; o >>= 1) {
            s  += __shfl_down_sync(0xffffffffu, s, o);
            ss += __shfl_down_sync(0xffffffffu, ss, o);
        }
        if (lane == 0) { rs[0] = s; rss[0] = ss; }
    }
    __syncthreads();
    float mu = rs[0] * (1.f / HID_);
    float var = rss[0] * (1.f / HID_) - mu * mu;
    float inv = rsqrtf(var + 1e-6f);
#pragma unroll
    for (int i = 0; i < 4; i++) {
        int c = tid + i * 256;
        out[base + c] = (y[i] - mu) * inv;
    }
}

// ---------------- launch ----------------
extern "C" void kernel_launch(void* const* d_in, const int* in_sizes, int n_in,
                              void* d_out, int out_size) {
    const float* x  = (const float*)d_in[0];
    const float* Wq = (const float*)d_in[1];
    const float* bq = (const float*)d_in[2];
    const float* Wk = (const float*)d_in[3];
    const float* bk = (const float*)d_in[4];
    const float* Wv = (const float*)d_in[5];
    const float* bv = (const float*)d_in[6];
    const float* Wo = (const float*)d_in[7];
    const float* bo = (const float*)d_in[8];
    const float* Wg = (const float*)d_in[9];
    const float* bg = (const float*)d_in[10];
    const float* Wc = (const float*)d_in[11];
    const float* bc = (const float*)d_in[12];
    const float* Ws = (const float*)d_in[13];
    const float* bs = (const float*)d_in[14];

    float* S; cudaGetSymbolAddress((void**)&S, g_scratch);
    int* idxp; cudaGetSymbolAddress((void**)&idxp, g_idx);

    float* Qf = S + OFF_QF;   float* Kf = S + OFF_KF;   float* Vf = S + OFF_VF;
    float* comp = S + OFF_COMP;
    float* Qc = S + OFF_QC;   float* Kc = S + OFF_KC;   float* Vc = S + OFF_VC;
    float* Sc = S + OFF_SC;   float* cPV = S + OFF_CPV;
    float* sQ = S + OFF_SQ;   float* sK = S + OFF_SK;   float* sV = S + OFF_SV;
    float* Ss = S + OFF_SS;   float* sPV = S + OFF_SPV;
    float* Sw = S + OFF_SW;   float* wPV = S + OFF_WPV;
    float* O  = S + OFF_O;
    float* gates = S + OFF_GATES;
    float* scores = S + OFF_SCORES;
    float* outp = (float*)d_out;

    const float SCALE = 0.125f;   // 1/sqrt(1024/16)

    // 1. gates + selection scores
    gates_scores_k<<<(int)(N_TOK / 4), 128>>>(x, Wg, bg, Ws, bs, gates, scores);
    // 2. exact top-k per batch
    topk_k<<<BATCH, 512>>>(scores, idxp);
    // 3. full Q/K/V projections (token-wise; reused by selected + window branches)
    run_gemm(x, Wq, bq, nullptr, Qf, (int)N_TOK, HID_, HID_, HID_, HID_, HID_, 1.f, 0, 0, 1, 1, 0,0,0,0,0,0, 0,0,0);
    run_gemm(x, Wk, bk, nullptr, Kf, (int)N_TOK, HID_, HID_, HID_, HID_, HID_, 1.f, 0, 0, 1, 1, 0,0,0,0,0,0, 0,0,0);
    run_gemm(x, Wv, bv, nullptr, Vf, (int)N_TOK, HID_, HID_, HID_, HID_, HID_, 1.f, 0, 0, 1, 1, 0,0,0,0,0,0, 0,0,0);
    // 4. compressed tokens: x viewed as (B*LC, 4H) row-major (contiguous reshape)
    run_gemm(x, Wc, bc, nullptr, comp, BATCH * LC, HID_, HC, HC, HID_, HID_, 1.f, 0, 0, 1, 1, 0,0,0,0,0,0, 0,0,0);
    // 5. compressed Q/K/V
    run_gemm(comp, Wq, bq, nullptr, Qc, BATCH * LC, HID_, HID_, HID_, HID_, HID_, 1.f, 0, 0, 1, 1, 0,0,0,0,0,0, 0,0,0);
    run_gemm(comp, Wk, bk, nullptr, Kc, BATCH * LC, HID_, HID_, HID_, HID_, HID_, 1.f, 0, 0, 1, 1, 0,0,0,0,0,0, 0,0,0);
    run_gemm(comp, Wv, bv, nullptr, Vc, BATCH * LC, HID_, HID_, HID_, HID_, HID_, 1.f, 0, 0, 1, 1, 0,0,0,0,0,0, 0,0,0);
    // 6. compressed attention scores (batched over B), softmax, P@V (gate0 fused)
    run_gemm(Qc, Kc, nullptr, nullptr, Sc, LC, LC, HID_, HID_, HID_, LC, SCALE, 1, 0,
             BATCH, 1, (long)LC*HID_, 0, (long)LC*HID_, 0, (long)LC*LC, 0, 0, 0, 0);
    softmax_k<<<BATCH * LC, 256>>>(Sc, LC);
    run_gemm(Sc, Vc, nullptr, gates, cPV, LC, HID_, LC, LC, HID_, HID_, 1.f, 0, 0,
             BATCH, 1, (long)LC*LC, 0, (long)LC*HID_, 0, (long)LC*HID_, 0, (long)SEQ*3, 0, 0);
    // 7. selected branch: gather rows of Q/K/V, attention (gate1 fused)
    gather_k<<<BATCH * KSEL, 256>>>(Qf, Kf, Vf, idxp, sQ, sK, sV);
    run_gemm(sQ, sK, nullptr, nullptr, Ss, KSEL, KSEL, HID_, HID_, HID_, KSEL, SCALE, 1, 0,
             BATCH, 1, (long)KSEL*HID_, 0, (long)KSEL*HID_, 0, (long)KSEL*KSEL, 0, 0, 0, 0);
    softmax_k<<<BATCH * KSEL, 256>>>(Ss, KSEL);
    run_gemm(Ss, sV, nullptr, gates, sPV, KSEL, HID_, KSEL, KSEL, HID_, HID_, 1.f, 0, 0,
             BATCH, 1, (long)KSEL*KSEL, 0, (long)KSEL*HID_, 0, (long)KSEL*HID_, 0, (long)SEQ*3, 0, 1);
    // 8. window branch: 64 batched 256x256 attentions over Q/K/V slices (stride 128),
    //    only windows 0..15 survive the truncation. (gate2 fused into P@V)
    run_gemm(Qf, Kf, nullptr, nullptr, Sw, WIN, WIN, HID_, HID_, HID_, WIN, SCALE, 1, 0,
             BATCH * NWIN, NWIN,
             (long)SEQ*HID_, (long)128*HID_,
             (long)SEQ*HID_, (long)128*HID_,
             (long)NWIN*WIN*WIN, (long)WIN*WIN, 0, 0, 0);
    softmax_k<<<BATCH * NWIN * WIN, 256>>>(Sw, WIN);
    run_gemm(Sw, Vf, nullptr, gates, wPV, WIN, HID_, WIN, WIN, HID_, HID_, 1.f, 0, 0,
             BATCH * NWIN, NWIN,
             (long)NWIN*WIN*WIN, (long)WIN*WIN,
             (long)SEQ*HID_, (long)128*HID_,
             (long)NWIN*WIN*HID_, (long)WIN*HID_,
             (long)SEQ*3, (long)WIN*3, 2);
    // 9. output projection, exploiting zero-padding of comp/sel branches
    run_gemm(wPV, Wo + (long)2048 * HID_, bo, nullptr, O, (int)N_TOK, HID_, HID_, HID_, HID_, HID_,
             1.f, 0, 0, 1, 1, 0,0,0,0,0,0, 0,0,0);
    run_gemm(cPV, Wo, nullptr, nullptr, O, LC, HID_, HID_, HID_, HID_, HID_, 1.f, 0, 1,
             BATCH, 1, (long)LC*HID_, 0, 0, 0, (long)SEQ*HID_, 0, 0, 0, 0);
    run_gemm(sPV, Wo + (long)1024 * HID_, nullptr, nullptr, O, KSEL, HID_, HID_, HID_, HID_, HID_, 1.f, 0, 1,
             BATCH, 1, (long)KSEL*HID_, 0, 0, 0, (long)SEQ*HID_, 0, 0, 0, 0);
    // 10. residual mix + layernorm
    final_ln_k<<<(int)N_TOK, 256>>>(O, x, outp);
}